// round 11
// baseline (speedup 1.0000x reference)
#include <cuda_runtime.h>
#include <cstdint>

#define KDIM 4096
#define NDIM 4096
#define MDIM 8192
#define KT 64
#define KITERS (KDIM / KT)      // 64
#define ASTRIDE 80
#define BSTRIDE 80
#define A_BUF_BYTES (128 * ASTRIDE)
#define B_BUF_BYTES (128 * BSTRIDE)
#define SM_BYTES (2 * A_BUF_BYTES + 2 * B_BUF_BYTES)  // 40960

// legal scratch: __device__ globals
__device__ int8_t gXq[(size_t)MDIM * KDIM];
__device__ int8_t gWq[(size_t)KDIM * NDIM];

// ---------------- input compaction: int32 -> int8 (verified transport) ----------------
__device__ __forceinline__ uint32_t pack4i(int4 v) {
    return (uint32_t)(uint8_t)(int8_t)v.x | ((uint32_t)(uint8_t)(int8_t)v.y << 8) |
           ((uint32_t)(uint8_t)(int8_t)v.z << 16) | ((uint32_t)(uint8_t)(int8_t)v.w << 24);
}

__global__ void __launch_bounds__(256)
convert_kernel(const int4* __restrict__ src, uint4* __restrict__ dst, int n16)
{
    int idx = blockIdx.x * 256 + threadIdx.x;
    if (idx >= n16) return;
    const int4* s = src + (size_t)idx * 4;
    uint4 out;
    out.x = pack4i(s[0]); out.y = pack4i(s[1]);
    out.z = pack4i(s[2]); out.w = pack4i(s[3]);
    dst[idx] = out;
}

// ---------------- GEMM ----------------
__device__ __forceinline__ void mma_s8(int* d, const uint32_t* a, const uint32_t* b) {
    asm volatile(
        "mma.sync.aligned.m16n8k32.row.col.s32.s8.s8.s32 "
        "{%0,%1,%2,%3}, {%4,%5,%6,%7}, {%8,%9}, {%0,%1,%2,%3};"
        : "+r"(d[0]), "+r"(d[1]), "+r"(d[2]), "+r"(d[3])
        : "r"(a[0]), "r"(a[1]), "r"(a[2]), "r"(a[3]), "r"(b[0]), "r"(b[1]));
}

// reference: round(acc * a * b) clipped to [-128,127]; half-even == jnp.round
__device__ __forceinline__ float quantf(int acc, float asc, float bsc) {
    float f = (float)acc * asc;
    f = f * bsc;
    int v = __float2int_rn(f);
    return (float)max(-128, min(127, v));
}

__global__ void __launch_bounds__(256, 1)
w8a8_imma_kernel(const float* __restrict__ Af, const float* __restrict__ Bf,
                 float* __restrict__ Out)
{
    __shared__ float bsc_s[128];
    __shared__ __align__(16) char sm[SM_BYTES];

    const int tid  = threadIdx.x;
    const int lane = tid & 31;
    const int wid  = tid >> 5;
    const int grp  = lane >> 2;
    const int qid  = lane & 3;

    const int m0 = (int)(blockIdx.x >> 5) * 128;
    const int n0 = (int)(blockIdx.x & 31) * 128;

    if (tid < 128) bsc_s[tid] = Bf[n0 + tid];
    const float asc = Af[0];

    const int8_t* __restrict__ X = gXq;
    const int8_t* __restrict__ W = gWq;

    char* As[2] = { sm, sm + A_BUF_BYTES };
    char* Bs[2] = { sm + 2 * A_BUF_BYTES, sm + 2 * A_BUF_BYTES + B_BUF_BYTES };

    const int ar = tid >> 1;
    const int ac = (tid & 1) * 32;
    const int8_t* gA = X + (size_t)(m0 + ar) * KDIM + ac;

    const int kb = tid >> 4;
    const int nb = tid & 15;
    const int8_t* gB = W + (size_t)(kb * 4) * NDIM + n0 + nb * 8;

    uint4 pa0, pa1;
    uint2 pb0, pb1, pb2, pb3;

#define PREFETCH(it)                                                          \
    {                                                                         \
        const int8_t* a_ = gA + (size_t)(it) * KT;                            \
        pa0 = *reinterpret_cast<const uint4*>(a_);                            \
        pa1 = *reinterpret_cast<const uint4*>(a_ + 16);                       \
        const int8_t* b_ = gB + (size_t)(it) * KT * NDIM;                     \
        pb0 = *reinterpret_cast<const uint2*>(b_);                            \
        pb1 = *reinterpret_cast<const uint2*>(b_ + (size_t)NDIM);             \
        pb2 = *reinterpret_cast<const uint2*>(b_ + (size_t)2 * NDIM);         \
        pb3 = *reinterpret_cast<const uint2*>(b_ + (size_t)3 * NDIM);         \
    }

#define STORE_STAGE(buf)                                                      \
    {                                                                         \
        *reinterpret_cast<uint4*>(As[buf] + ar * ASTRIDE + ac) = pa0;         \
        *reinterpret_cast<uint4*>(As[buf] + ar * ASTRIDE + ac + 16) = pa1;    \
        uint32_t c[8];                                                        \
        {                                                                     \
            uint32_t t0 = __byte_perm(pb0.x, pb1.x, 0x5140);                  \
            uint32_t t1 = __byte_perm(pb0.x, pb1.x, 0x7362);                  \
            uint32_t t2 = __byte_perm(pb2.x, pb3.x, 0x5140);                  \
            uint32_t t3 = __byte_perm(pb2.x, pb3.x, 0x7362);                  \
            c[0] = __byte_perm(t0, t2, 0x5410);                               \
            c[1] = __byte_perm(t0, t2, 0x7632);                               \
            c[2] = __byte_perm(t1, t3, 0x5410);                               \
            c[3] = __byte_perm(t1, t3, 0x7632);                               \
        }                                                                     \
        {                                                                     \
            uint32_t t0 = __byte_perm(pb0.y, pb1.y, 0x5140);                  \
            uint32_t t1 = __byte_perm(pb0.y, pb1.y, 0x7362);                  \
            uint32_t t2 = __byte_perm(pb2.y, pb3.y, 0x5140);                  \
            uint32_t t3 = __byte_perm(pb2.y, pb3.y, 0x7362);                  \
            c[4] = __byte_perm(t0, t2, 0x5410);                               \
            c[5] = __byte_perm(t0, t2, 0x7632);                               \
            c[6] = __byte_perm(t1, t3, 0x5410);                               \
            c[7] = __byte_perm(t1, t3, 0x7632);                               \
        }                                                                     \
        char* bb_ = Bs[buf] + kb * 4;                                         \
        _Pragma("unroll")                                                     \
        for (int ii = 0; ii < 8; ii++) {                                      \
            int idx = (ii + nb) & 7;                                          \
            *reinterpret_cast<uint32_t*>(bb_ + (nb * 8 + idx) * BSTRIDE) = c[idx]; \
        }                                                                     \
    }

    const int mw = (wid >> 1) * 32;
    const int nw = (wid & 1) * 64;

    int acc[2][8][4];
#pragma unroll
    for (int mt = 0; mt < 2; mt++)
#pragma unroll
        for (int nt = 0; nt < 8; nt++)
#pragma unroll
            for (int r = 0; r < 4; r++) acc[mt][nt][r] = 0;

    PREFETCH(0);
    STORE_STAGE(0);
    __syncthreads();

#pragma unroll 1
    for (int it = 0; it < KITERS; it++) {
        const int buf = it & 1;
        if (it + 1 < KITERS) PREFETCH(it + 1);

#pragma unroll
        for (int kstep = 0; kstep < 2; kstep++) {
            uint32_t a[2][4];
            {
                const char* ab = As[buf] + (mw + grp) * ASTRIDE + qid * 4 + kstep * 32;
#pragma unroll
                for (int mt = 0; mt < 2; mt++) {
                    const char* p = ab + mt * 16 * ASTRIDE;
                    a[mt][0] = *reinterpret_cast<const uint32_t*>(p);
                    a[mt][1] = *reinterpret_cast<const uint32_t*>(p + 8 * ASTRIDE);
                    a[mt][2] = *reinterpret_cast<const uint32_t*>(p + 16);
                    a[mt][3] = *reinterpret_cast<const uint32_t*>(p + 8 * ASTRIDE + 16);
                }
            }
            uint32_t b[8][2];
            {
                const char* bb = Bs[buf] + (nw + grp) * BSTRIDE + qid * 4 + kstep * 32;
#pragma unroll
                for (int nt = 0; nt < 8; nt++) {
                    b[nt][0] = *reinterpret_cast<const uint32_t*>(bb + nt * 8 * BSTRIDE);
                    b[nt][1] = *reinterpret_cast<const uint32_t*>(bb + nt * 8 * BSTRIDE + 16);
                }
            }
#pragma unroll
            for (int mt = 0; mt < 2; mt++)
#pragma unroll
                for (int nt = 0; nt < 8; nt++)
                    mma_s8(acc[mt][nt], a[mt], b[nt]);
        }

        if (it + 1 < KITERS) STORE_STAGE(buf ^ 1);
        __syncthreads();
    }

    // ---------------- Epilogue: FLOAT32 output (comparator dtype, measured R10) ----
#pragma unroll
    for (int mt = 0; mt < 2; mt++) {
        const int r0 = m0 + mw + mt * 16 + grp;
#pragma unroll
        for (int nt = 0; nt < 8; nt++) {
            const int col = n0 + nw + nt * 8 + qid * 2;
            const float2 bb = *reinterpret_cast<const float2*>(&bsc_s[col - n0]);
            const int* v = acc[mt][nt];
            float2 lo = make_float2(quantf(v[0], asc, bb.x), quantf(v[1], asc, bb.y));
            float2 hi = make_float2(quantf(v[2], asc, bb.x), quantf(v[3], asc, bb.y));
            *reinterpret_cast<float2*>(Out + (size_t)r0 * NDIM + col) = lo;
            *reinterpret_cast<float2*>(Out + (size_t)(r0 + 8) * NDIM + col) = hi;
        }
    }
}

extern "C" void kernel_launch(void* const* d_in, const int* in_sizes, int n_in,
                              void* d_out, int out_size)
{
    // Measured (R10 diagnostics): positional order x, weight, a, b;
    // x/w transported as int32, a/b as float32, output compared as float32.
    const int4*  X  = (const int4*)d_in[0];
    const int4*  W  = (const int4*)d_in[1];
    const float* Af = (const float*)d_in[2];
    const float* Bf = (const float*)d_in[3];
    float* Out = (float*)d_out;

    uint4* xq; cudaGetSymbolAddress((void**)&xq, gXq);
    uint4* wq; cudaGetSymbolAddress((void**)&wq, gWq);

    const int xN16 = (MDIM * KDIM) / 16;   // 2097152
    const int wN16 = (KDIM * NDIM) / 16;   // 1048576
    convert_kernel<<<xN16 / 256, 256>>>(X, xq, xN16);
    convert_kernel<<<wN16 / 256, 256>>>(W, wq, wN16);

    const int grid = (MDIM / 128) * (NDIM / 128);  // 2048
    w8a8_imma_kernel<<<grid, 256>>>(Af, Bf, Out);
}

// round 12
// speedup vs baseline: 1.0121x; 1.0121x over previous
#include <cuda_runtime.h>
#include <cstdint>

#define KDIM 4096
#define NDIM 4096
#define MDIM 8192
#define KT 64
#define KITERS (KDIM / KT)      // 64
#define ASTRIDE 96              // conflict-free for LDS.64 fragment reads
#define BSTRIDE 96
#define A_BUF_BYTES (128 * ASTRIDE)   // 12288
#define B_BUF_BYTES (128 * BSTRIDE)   // 12288
#define SM_BYTES (2 * A_BUF_BYTES + 2 * B_BUF_BYTES)  // 49152 (48KB static max)

// legal scratch: __device__ globals
__device__ int8_t gXq[(size_t)MDIM * KDIM];
__device__ int8_t gWq[(size_t)KDIM * NDIM];

// ---------------- merged input compaction: int32 -> int8 ----------------
__device__ __forceinline__ uint32_t pack4i(int4 v) {
    return (uint32_t)(uint8_t)(int8_t)v.x | ((uint32_t)(uint8_t)(int8_t)v.y << 8) |
           ((uint32_t)(uint8_t)(int8_t)v.z << 16) | ((uint32_t)(uint8_t)(int8_t)v.w << 24);
}

#define XN16 ((MDIM * KDIM) / 16)   // 2097152
#define WN16 ((KDIM * NDIM) / 16)   // 1048576

__global__ void __launch_bounds__(256)
convert2_kernel(const int4* __restrict__ x, const int4* __restrict__ w,
                uint4* __restrict__ xq, uint4* __restrict__ wq)
{
    int idx = blockIdx.x * 256 + threadIdx.x;
    const int4* s;
    uint4* d;
    if (idx < XN16) {
        s = x + (size_t)idx * 4;
        d = xq + idx;
    } else {
        int j = idx - XN16;
        s = w + (size_t)j * 4;
        d = wq + j;
    }
    uint4 out;
    out.x = pack4i(s[0]); out.y = pack4i(s[1]);
    out.z = pack4i(s[2]); out.w = pack4i(s[3]);
    *d = out;
}

// ---------------- GEMM ----------------
__device__ __forceinline__ void mma_s8(int* d, const uint32_t* a, const uint32_t* b) {
    asm volatile(
        "mma.sync.aligned.m16n8k32.row.col.s32.s8.s8.s32 "
        "{%0,%1,%2,%3}, {%4,%5,%6,%7}, {%8,%9}, {%0,%1,%2,%3};"
        : "+r"(d[0]), "+r"(d[1]), "+r"(d[2]), "+r"(d[3])
        : "r"(a[0]), "r"(a[1]), "r"(a[2]), "r"(a[3]), "r"(b[0]), "r"(b[1]));
}

__device__ __forceinline__ float quantf(int acc, float asc, float bsc) {
    float f = (float)acc * asc;
    f = f * bsc;
    int v = __float2int_rn(f);    // half-even == jnp.round
    return (float)max(-128, min(127, v));
}

// SMEM fragment layouts (pair-interleaved so (k, k+16) chunks are adjacent):
//   A: row*96 + s*32 + q*8 + {0:chunk q | 4:chunk q+4},  q = (k%32)/4 in 0..3
//   B: col*96 + s*32 + q*8 + {0:b0 | 4:b1}
// Reader: one LDS.64 per fragment pair, conflict-free per half-warp phase.

__global__ void __launch_bounds__(256, 1)
w8a8_imma_kernel(const float* __restrict__ Af, const float* __restrict__ Bf,
                 float* __restrict__ Out)
{
    __shared__ __align__(16) char sm[SM_BYTES];

    const int tid  = threadIdx.x;
    const int lane = tid & 31;
    const int wid  = tid >> 5;
    const int grp  = lane >> 2;
    const int qid  = lane & 3;

    const int m0 = (int)(blockIdx.x >> 5) * 128;
    const int n0 = (int)(blockIdx.x & 31) * 128;

    const float asc = Af[0];

    const int8_t* __restrict__ X = gXq;
    const int8_t* __restrict__ W = gWq;

    char* As[2] = { sm, sm + A_BUF_BYTES };
    char* Bs[2] = { sm + 2 * A_BUF_BYTES, sm + 2 * A_BUF_BYTES + B_BUF_BYTES };

    // A copy mapping: thread -> (row ar, kstep half s_a)
    const int ar  = tid >> 1;
    const int s_a = tid & 1;
    const int8_t* gA = X + (size_t)(m0 + ar) * KDIM + s_a * 32;

    // B copy mapping: thread -> 4 k-rows x 8 cols, transposed on store
    const int kb = tid >> 4;           // 0..15 (k-chunk index, k = kb*4)
    const int nb = tid & 15;
    const int8_t* gB = W + (size_t)(kb * 4) * NDIM + n0 + nb * 8;
    const int q_b = kb & 7;
    const int s_b = kb >> 3;

    uint4 pa0, pa1;
    uint2 pb0, pb1, pb2, pb3;

#define PREFETCH(it)                                                          \
    {                                                                         \
        const int8_t* a_ = gA + (size_t)(it) * KT;                            \
        pa0 = *reinterpret_cast<const uint4*>(a_);                            \
        pa1 = *reinterpret_cast<const uint4*>(a_ + 16);                       \
        const int8_t* b_ = gB + (size_t)(it) * KT * NDIM;                     \
        pb0 = *reinterpret_cast<const uint2*>(b_);                            \
        pb1 = *reinterpret_cast<const uint2*>(b_ + (size_t)NDIM);             \
        pb2 = *reinterpret_cast<const uint2*>(b_ + (size_t)2 * NDIM);         \
        pb3 = *reinterpret_cast<const uint2*>(b_ + (size_t)3 * NDIM);         \
    }

#define STORE_STAGE(buf)                                                      \
    {                                                                         \
        /* A: interleave so (q, q+4) pairs are adjacent 4B words */           \
        char* arow = As[buf] + ar * ASTRIDE + s_a * 32;                       \
        *reinterpret_cast<uint4*>(arow) =                                     \
            make_uint4(pa0.x, pa1.x, pa0.y, pa1.y);                           \
        *reinterpret_cast<uint4*>(arow + 16) =                                \
            make_uint4(pa0.z, pa1.z, pa0.w, pa1.w);                           \
        uint32_t c[8];                                                        \
        {                                                                     \
            uint32_t t0 = __byte_perm(pb0.x, pb1.x, 0x5140);                  \
            uint32_t t1 = __byte_perm(pb0.x, pb1.x, 0x7362);                  \
            uint32_t t2 = __byte_perm(pb2.x, pb3.x, 0x5140);                  \
            uint32_t t3 = __byte_perm(pb2.x, pb3.x, 0x7362);                  \
            c[0] = __byte_perm(t0, t2, 0x5410);                               \
            c[1] = __byte_perm(t0, t2, 0x7632);                               \
            c[2] = __byte_perm(t1, t3, 0x5410);                               \
            c[3] = __byte_perm(t1, t3, 0x7632);                               \
        }                                                                     \
        {                                                                     \
            uint32_t t0 = __byte_perm(pb0.y, pb1.y, 0x5140);                  \
            uint32_t t1 = __byte_perm(pb0.y, pb1.y, 0x7362);                  \
            uint32_t t2 = __byte_perm(pb2.y, pb3.y, 0x5140);                  \
            uint32_t t3 = __byte_perm(pb2.y, pb3.y, 0x7362);                  \
            c[4] = __byte_perm(t0, t2, 0x5410);                               \
            c[5] = __byte_perm(t0, t2, 0x7632);                               \
            c[6] = __byte_perm(t1, t3, 0x5410);                               \
            c[7] = __byte_perm(t1, t3, 0x7632);                               \
        }                                                                     \
        char* bb_ = Bs[buf] + s_b * 32 + (q_b & 3) * 8 + ((q_b & 4) ? 4 : 0); \
        _Pragma("unroll")                                                     \
        for (int ii = 0; ii < 8; ii++) {                                      \
            int idx = (ii + nb) & 7;                                          \
            *reinterpret_cast<uint32_t*>(bb_ + (nb * 8 + idx) * BSTRIDE) = c[idx]; \
        }                                                                     \
    }

    const int mw = (wid >> 1) * 32;
    const int nw = (wid & 1) * 64;

    int acc[2][8][4];
#pragma unroll
    for (int mt = 0; mt < 2; mt++)
#pragma unroll
        for (int nt = 0; nt < 8; nt++)
#pragma unroll
            for (int r = 0; r < 4; r++) acc[mt][nt][r] = 0;

    PREFETCH(0);
    STORE_STAGE(0);
    __syncthreads();

#pragma unroll 1
    for (int it = 0; it < KITERS; it++) {
        const int buf = it & 1;
        if (it + 1 < KITERS) PREFETCH(it + 1);

#pragma unroll
        for (int kstep = 0; kstep < 2; kstep++) {
            // A fragments: {a0,a2} and {a1,a3} via LDS.64
            uint32_t a[2][4];
#pragma unroll
            for (int mt = 0; mt < 2; mt++) {
                const char* p = As[buf] + (mw + mt * 16 + grp) * ASTRIDE +
                                kstep * 32 + qid * 8;
                uint2 lo = *reinterpret_cast<const uint2*>(p);
                uint2 hi = *reinterpret_cast<const uint2*>(p + 8 * ASTRIDE);
                a[mt][0] = lo.x; a[mt][1] = hi.x;
                a[mt][2] = lo.y; a[mt][3] = hi.y;
            }
            // B fragments: {b0,b1} via LDS.64
            uint32_t b[8][2];
#pragma unroll
            for (int nt = 0; nt < 8; nt++) {
                const char* p = Bs[buf] + (nw + nt * 8 + grp) * BSTRIDE +
                                kstep * 32 + qid * 8;
                uint2 v = *reinterpret_cast<const uint2*>(p);
                b[nt][0] = v.x; b[nt][1] = v.y;
            }
#pragma unroll
            for (int mt = 0; mt < 2; mt++)
#pragma unroll
                for (int nt = 0; nt < 8; nt++)
                    mma_s8(acc[mt][nt], a[mt], b[nt]);
        }

        if (it + 1 < KITERS) STORE_STAGE(buf ^ 1);
        __syncthreads();
    }

    // ---------------- Epilogue: float32 output ----------------
#pragma unroll
    for (int mt = 0; mt < 2; mt++) {
        const int r0 = m0 + mw + mt * 16 + grp;
#pragma unroll
        for (int nt = 0; nt < 8; nt++) {
            const int col = n0 + nw + nt * 8 + qid * 2;
            const float2 bb = *reinterpret_cast<const float2*>(Bf + col);
            const int* v = acc[mt][nt];
            float2 lo = make_float2(quantf(v[0], asc, bb.x), quantf(v[1], asc, bb.y));
            float2 hi = make_float2(quantf(v[2], asc, bb.x), quantf(v[3], asc, bb.y));
            *reinterpret_cast<float2*>(Out + (size_t)r0 * NDIM + col) = lo;
            *reinterpret_cast<float2*>(Out + (size_t)(r0 + 8) * NDIM + col) = hi;
        }
    }
}

extern "C" void kernel_launch(void* const* d_in, const int* in_sizes, int n_in,
                              void* d_out, int out_size)
{
    // Measured (R10): positional x, weight, a, b; x/w int32, a/b f32, out f32.
    const int4*  X  = (const int4*)d_in[0];
    const int4*  W  = (const int4*)d_in[1];
    const float* Af = (const float*)d_in[2];
    const float* Bf = (const float*)d_in[3];
    float* Out = (float*)d_out;

    uint4* xq; cudaGetSymbolAddress((void**)&xq, gXq);
    uint4* wq; cudaGetSymbolAddress((void**)&wq, gWq);

    convert2_kernel<<<(XN16 + WN16) / 256, 256>>>(X, W, xq, wq);

    const int grid = (MDIM / 128) * (NDIM / 128);  // 2048
    w8a8_imma_kernel<<<grid, 256>>>(Af, Bf, Out);
}